// round 9
// baseline (speedup 1.0000x reference)
#include <cuda_runtime.h>
#include <math.h>

// Problem constants (fixed benchmark shapes)
#define N_PTS   50000
#define C_FEAT  128
#define HF      480
#define WF      640
#define IMW     640
#define IMH     480
#define HW      (HF*WF)
#define NITERS  10

#define MTHREADS 256
#define NWARP    (MTHREADS/32)
#define MAXB     1184

// ---------------- persistent device state ----------------
// Packed pixel-major maps: per pixel 96 float4 = [fm(32 f4) | gx(32 f4) | gy(32 f4)]
__device__ float4 g_packed[(size_t)HW * 96];

__device__ double   g_part[29][MAXB];   // transposed: coalesced reads in block0 reduce
__device__ float    g_Rc[9], g_tc[3];   // candidate pose (block0 -> all blocks)
__device__ unsigned g_count = 0;        // barrier arrival counter (reset by releaser)
__device__ unsigned g_gen   = 0;        // barrier generation (monotonic, replay-safe)

// ---------------- transpose (C,H,W) x3 -> (pix, map, C) ----------------
__global__ __launch_bounds__(256) void transpose_kernel(
    const float* __restrict__ fm, const float* __restrict__ gx, const float* __restrict__ gy)
{
    __shared__ float sh[32][C_FEAT + 1];
    int b    = blockIdx.x;            // (HW/32)*3 blocks
    int map  = b / (HW / 32);
    int tile = b % (HW / 32);
    int pix0 = tile * 32;
    const float* src = (map == 0) ? fm : (map == 1) ? gx : gy;

    int t = threadIdx.x, lane = t & 31, grp = t >> 5;   // 8 groups
    #pragma unroll
    for (int cb = 0; cb < C_FEAT; cb += 8) {
        int ch = cb + grp;
        sh[lane][ch] = src[(size_t)ch * HW + pix0 + lane];
    }
    __syncthreads();
    float* out = (float*)g_packed;
    #pragma unroll
    for (int pb = 0; pb < 32; pb += 8) {
        int p = pb + grp;
        size_t base = (size_t)(pix0 + p) * 384 + (size_t)map * 128;
        #pragma unroll
        for (int k = 0; k < 4; k++)
            out[base + k * 32 + lane] = sh[p][k * 32 + lane];
    }
}

// ---------------- software grid barrier ----------------
__device__ __forceinline__ void gbar(int grid) {
    __syncthreads();
    if (threadIdx.x == 0) {
        unsigned gen = *(volatile unsigned*)&g_gen;
        __threadfence();
        unsigned old = atomicAdd(&g_count, 1u);
        if (old == (unsigned)grid - 1u) {
            g_count = 0;
            __threadfence();
            atomicAdd(&g_gen, 1u);
        } else {
            while (*(volatile unsigned*)&g_gen == gen) { }
        }
        __threadfence();
    }
    __syncthreads();
}

// ---------------- L1 prefetch helper (no destination register!) ----------------
__device__ __forceinline__ void pf_l1(const void* p) {
    asm volatile("prefetch.global.L1 [%0];" :: "l"(p));
}

// ---------------- warp-parallel 6x6 LM solve + pose compose ----------------
// Rows of the augmented system live on lanes 0..5. Op-for-op identical to the
// single-thread Gauss-Jordan with partial pivoting (same pivot tie-breaks).
__device__ __forceinline__ void warp_solve(
    const double* __restrict__ GH, float lam_f, float lr_f,
    const float* __restrict__ Rcur, const float* __restrict__ tcur, int lane)
{
    double row[7];
    if (lane < 6) {
        #pragma unroll
        for (int j = 0; j < 7; j++) row[j] = 0.0;
        #pragma unroll
        for (int j = 0; j < 6; j++) {
            int k = lane < j ? lane : j;
            int l = lane < j ? j : lane;
            int idx = 6 + (6*k - (k*(k-1))/2) + (l - k);
            row[j] = GH[idx];
        }
        row[6] = GH[lane];
        double lam = (double)lam_f;
        row[lane] += lam * (row[lane] + 1e-9);
    } else {
        #pragma unroll
        for (int j = 0; j < 7; j++) row[j] = 0.0;
    }

    for (int k = 0; k < 6; k++) {
        // pivot argmax over rows k..5 (smallest index wins ties, like the serial scan)
        double av = (lane < 6 && lane >= k) ? fabs(row[k]) : -1.0;
        int best = lane;
        #pragma unroll
        for (int o = 16; o; o >>= 1) {
            double av2 = __shfl_xor_sync(0xffffffffu, av, o);
            int    b2  = __shfl_xor_sync(0xffffffffu, best, o);
            if (av2 > av || (av2 == av && b2 < best)) { av = av2; best = b2; }
        }
        int p = best;
        if (p != k) {
            #pragma unroll
            for (int j = 0; j < 7; j++) {
                double vk = __shfl_sync(0xffffffffu, row[j], k);
                double vp = __shfl_sync(0xffffffffu, row[j], p);
                if (lane == k) row[j] = vp;
                else if (lane == p) row[j] = vk;
            }
        }
        double pivval = __shfl_sync(0xffffffffu, row[k], k);
        double inv = 1.0 / pivval;
        if (lane == k) {
            #pragma unroll
            for (int j = 0; j < 7; j++) row[j] *= inv;
        }
        double prow[7];
        #pragma unroll
        for (int j = 0; j < 7; j++) prow[j] = __shfl_sync(0xffffffffu, row[j], k);
        if (lane < 6 && lane != k) {
            double f = row[k];
            #pragma unroll
            for (int j = 0; j < 7; j++) row[j] -= f * prow[j];
        }
    }

    // gather solution to all lanes
    double xr = row[6];
    double x[6];
    #pragma unroll
    for (int j = 0; j < 6; j++) x[j] = __shfl_sync(0xffffffffu, xr, j);

    if (lane == 0) {
        double lr = (double)lr_f;
        double dt0 = -lr * x[0], dt1 = -lr * x[1], dt2 = -lr * x[2];
        double w0  = -lr * x[3], w1  = -lr * x[4], w2  = -lr * x[5];

        double th2 = w0*w0 + w1*w1 + w2*w2;
        double th  = sqrt(th2 + 1e-24);
        double a, b;
        if (th < 1e-4) { a = 1.0 - th2 / 6.0; b = 0.5 - th2 / 24.0; }
        else           { a = sin(th) / th;    b = (1.0 - cos(th)) / (th2 + 1e-24); }
        double W[9]  = {0, -w2, w1,  w2, 0, -w0,  -w1, w0, 0};
        double W2[9];
        for (int r = 0; r < 3; r++)
            for (int c = 0; c < 3; c++) {
                double s = 0;
                for (int kq = 0; kq < 3; kq++) s += W[r*3+kq] * W[kq*3+c];
                W2[r*3+c] = s;
            }
        double dr[9];
        for (int i = 0; i < 9; i++) dr[i] = a * W[i] + b * W2[i];
        dr[0] += 1.0; dr[4] += 1.0; dr[8] += 1.0;

        double Rc[9], tc[3];
        for (int r = 0; r < 3; r++)
            for (int c = 0; c < 3; c++) {
                double s = 0;
                for (int kq = 0; kq < 3; kq++) s += dr[r*3+kq] * (double)Rcur[kq*3+c];
                Rc[r*3+c] = s;
            }
        for (int r = 0; r < 3; r++) {
            double s = 0;
            for (int kq = 0; kq < 3; kq++) s += dr[r*3+kq] * (double)tcur[kq];
            tc[r] = s;
        }
        tc[0] += dt0; tc[1] += dt1; tc[2] += dt2;

        for (int i = 0; i < 9; i++) g_Rc[i] = (float)Rc[i];
        for (int i = 0; i < 3; i++) g_tc[i] = (float)tc[i];
    }
}

// ---------------- persistent mega-kernel ----------------
__global__ __launch_bounds__(MTHREADS, 3)
void mega_kernel(const float* __restrict__ pts, const float* __restrict__ fref,
                 const float* __restrict__ Kmat, const float* __restrict__ R0,
                 const float* __restrict__ t0, float* __restrict__ out, int grid)
{
    __shared__ int    s_pix[MTHREADS];
    __shared__ float  s_X[MTHREADS], s_Y[MTHREADS], s_Z[MTHREADS];
    __shared__ int    s_idx[MTHREADS];
    __shared__ int    s_wcnt[NWARP];
    __shared__ double sred[NWARP][29];
    __shared__ double red[29];
    __shared__ double sGH[27];
    __shared__ float  sRcur[9], stcur[3];
    __shared__ float  sstate[2];        // lam, lr
    __shared__ double sprev;

    const float fx = Kmat[0], cx = Kmat[2], fy = Kmat[4], cy = Kmat[5];
    const int lane = threadIdx.x & 31;
    const int wrp  = threadIdx.x >> 5;
    const float4* frf4 = (const float4*)fref;

    const int chunk = (N_PTS + grid - 1) / grid;
    const int base  = blockIdx.x * chunk;
    const int myn   = (base < N_PTS) ? min(chunk, N_PTS - base) : 0;

    for (int step = 0; step <= NITERS; step++) {
        const bool doGH = (step < NITERS);
        // ---- pose to evaluate ----
        float Rl[9], tl[3];
        if (step == 0) {
            #pragma unroll
            for (int i = 0; i < 9; i++) Rl[i] = R0[i];
            #pragma unroll
            for (int i = 0; i < 3; i++) tl[i] = t0[i];
        } else {
            #pragma unroll
            for (int i = 0; i < 9; i++) Rl[i] = g_Rc[i];
            #pragma unroll
            for (int i = 0; i < 3; i++) tl[i] = g_tc[i];
        }

        // per-lane f32 accumulators (no per-point cross-lane reduction)
        float ga[6]  = {0,0,0,0,0,0};
        float ha[21] = {0,0,0,0,0,0,0,0,0,0,0,0,0,0,0,0,0,0,0,0,0};
        double acost = 0.0;
        int    validtot = 0;

        for (int tb = 0; tb < myn; tb += MTHREADS) {
            // ===== Phase A: thread-parallel projection + deterministic compaction =====
            int tloc = tb + threadIdx.x;
            bool valid = false;
            float X = 0.f, Y = 0.f, Z = 0.f;
            int pix = 0;
            if (tloc < myn) {
                int i = base + tloc;
                float X0 = pts[3*i], Y0 = pts[3*i+1], Z0 = pts[3*i+2];
                X = Rl[0]*X0 + Rl[1]*Y0 + Rl[2]*Z0 + tl[0];
                Y = Rl[3]*X0 + Rl[4]*Y0 + Rl[5]*Z0 + tl[1];
                Z = Rl[6]*X0 + Rl[7]*Y0 + Rl[8]*Z0 + tl[2];
                float u = (fx*X + cx*Z) / Z;
                float v = (fy*Y + cy*Z) / Z;
                u = fminf(fmaxf(u, -1e6f), 1e6f);
                v = fminf(fmaxf(v, -1e6f), 1e6f);
                int px = (int)rintf(u) - 1;
                int py = (int)rintf(v) - 1;
                valid = (px >= 0) && (py >= 0) && (px < IMW) && (py < IMH);
                pix = py * WF + px;
            }
            unsigned bal = __ballot_sync(0xffffffffu, valid);
            if (lane == 0) s_wcnt[wrp] = __popc(bal);
            __syncthreads();
            int off = 0, total = 0;
            #pragma unroll
            for (int w2 = 0; w2 < NWARP; w2++) {
                int c2 = s_wcnt[w2];
                if (w2 < wrp) off += c2;
                total += c2;
            }
            int pos = off + __popc(bal & ((1u << lane) - 1u));
            if (valid) {
                s_pix[pos] = pix; s_X[pos] = X; s_Y[pos] = Y; s_Z[pos] = Z;
                s_idx[pos] = base + tloc;
            }
            __syncthreads();
            validtot += total;

            // ===== Phase B: gather -> FMA stream, register-free L1 prefetch =====
            // warm prefetch for the first iteration's +NWARP neighbor
            {
                int j1 = wrp + NWARP;
                if (j1 < total && (lane & 7) == 0) {
                    const char* pn = (const char*)(g_packed + (size_t)s_pix[j1] * 96) + lane * 16;
                    pf_l1(pn);
                    pf_l1(pn + 512);
                    pf_l1(pn + 1024);
                    pf_l1((const char*)(frf4 + (size_t)s_idx[j1] * 32) + lane * 16);
                }
            }
            for (int j = wrp; j < total; j += NWARP) {
                // prefetch 2 iterations ahead (L2 latency ~250cyc covered)
                int j2 = j + 2 * NWARP;
                if (j2 < total && (lane & 7) == 0) {
                    const char* pn = (const char*)(g_packed + (size_t)s_pix[j2] * 96) + lane * 16;
                    pf_l1(pn);
                    if (doGH) { pf_l1(pn + 512); pf_l1(pn + 1024); }
                    pf_l1((const char*)(frf4 + (size_t)s_idx[j2] * 32) + lane * 16);
                }

                const float4* pb = g_packed + (size_t)s_pix[j] * 96;
                float4 f  = pb[lane];
                float4 fr = frf4[(size_t)s_idx[j] * 32 + lane];

                float ex = f.x - fr.x, ey = f.y - fr.y, ez = f.z - fr.z, ew = f.w - fr.w;
                float e2 = ex*ex + ey*ey + ez*ez + ew*ew;
                acost += (double)e2;

                if (doGH) {
                    float4 a  = pb[32 + lane];
                    float4 bb = pb[64 + lane];
                    // per-lane partial dot products (4 channels each)
                    float sxe = a.x*ex + a.y*ey + a.z*ez + a.w*ew;
                    float sye = bb.x*ex + bb.y*ey + bb.z*ez + bb.w*ew;
                    float sxx = a.x*a.x + a.y*a.y + a.z*a.z + a.w*a.w;
                    float sxy = a.x*bb.x + a.y*bb.y + a.z*bb.z + a.w*bb.w;
                    float syy = bb.x*bb.x + bb.y*bb.y + bb.z*bb.z + bb.w*bb.w;

                    // warp-uniform A coefficients
                    float Xp = s_X[j], Yp = s_Y[j], Zp = s_Z[j];
                    float Zs  = (fabsf(Zp) > 1e-6f) ? Zp : 1e-6f;
                    float iz  = 1.0f / Zs;
                    float iz2 = iz * iz;
                    float u0 =  fx * iz;
                    float u2 = -fx * Xp * iz2;
                    float u3 = -fx * Xp * Yp * iz2;
                    float u4 =  fx * Zp * iz + fx * Xp * Xp * iz2;
                    float u5 = -fx * Yp * iz;
                    float v1 =  fy * iz;
                    float v2 = -fy * Yp * iz2;
                    float v3 = -fy * Zp * iz - fy * Yp * Yp * iz2;
                    float v4 =  fy * Xp * Yp * iz2;
                    float v5 =  fy * Xp * iz;

                    ga[0] += sxe * u0;
                    ga[1] += sye * v1;
                    ga[2] += sxe * u2 + sye * v2;
                    ga[3] += sxe * u3 + sye * v3;
                    ga[4] += sxe * u4 + sye * v4;
                    ga[5] += sxe * u5 + sye * v5;

                    // Cholesky of per-lane 2x2 Gram -> rank-2 as x x^T + y y^T
                    float rs    = rsqrtf(sxx + 1e-30f);
                    float alpha = sxx * rs;
                    float beta  = sxy * rs;
                    float g2m   = fmaxf(syy - beta * beta, 0.0f);
                    float gamma = sqrtf(g2m);

                    float x0 = alpha * u0;
                    float x1 = beta  * v1;
                    float x2 = alpha * u2 + beta * v2;
                    float x3 = alpha * u3 + beta * v3;
                    float x4 = alpha * u4 + beta * v4;
                    float x5 = alpha * u5 + beta * v5;
                    float y1 = gamma * v1;
                    float y2 = gamma * v2;
                    float y3 = gamma * v3;
                    float y4 = gamma * v4;
                    float y5 = gamma * v5;

                    ha[0]  += x0*x0;
                    ha[1]  += x0*x1;
                    ha[2]  += x0*x2;
                    ha[3]  += x0*x3;
                    ha[4]  += x0*x4;
                    ha[5]  += x0*x5;
                    ha[6]  += x1*x1 + y1*y1;
                    ha[7]  += x1*x2 + y1*y2;
                    ha[8]  += x1*x3 + y1*y3;
                    ha[9]  += x1*x4 + y1*y4;
                    ha[10] += x1*x5 + y1*y5;
                    ha[11] += x2*x2 + y2*y2;
                    ha[12] += x2*x3 + y2*y3;
                    ha[13] += x2*x4 + y2*y4;
                    ha[14] += x2*x5 + y2*y5;
                    ha[15] += x3*x3 + y3*y3;
                    ha[16] += x3*x4 + y3*y4;
                    ha[17] += x3*x5 + y3*y5;
                    ha[18] += x4*x4 + y4*y4;
                    ha[19] += x4*x5 + y4*y5;
                    ha[20] += x5*x5 + y5*y5;
                }
            }
            __syncthreads();   // protect smem before next tile's Phase A
        }

        // ---- once-per-step cross-lane reduction ----
        #pragma unroll
        for (int v = 0; v < 6; v++) {
            float s = ga[v];
            #pragma unroll
            for (int o = 16; o; o >>= 1) s += __shfl_xor_sync(0xffffffffu, s, o);
            if (lane == 0) sred[wrp][v] = (double)s;
        }
        #pragma unroll
        for (int v = 0; v < 21; v++) {
            float s = ha[v];
            #pragma unroll
            for (int o = 16; o; o >>= 1) s += __shfl_xor_sync(0xffffffffu, s, o);
            if (lane == 0) sred[wrp][6 + v] = (double)s;
        }
        {
            double s = acost;
            #pragma unroll
            for (int o = 16; o; o >>= 1) s += __shfl_xor_sync(0xffffffffu, s, o);
            if (lane == 0) sred[wrp][27] = s;
        }
        __syncthreads();
        if (threadIdx.x < 28) {
            double s = 0.0;
            #pragma unroll
            for (int jj = 0; jj < NWARP; jj++) s += sred[jj][threadIdx.x];
            g_part[threadIdx.x][blockIdx.x] = s;
        }
        if (threadIdx.x == 28) g_part[28][blockIdx.x] = (double)validtot;
        gbar(grid);

        // ---- block0: reduce partials (coalesced), accept, next candidate ----
        if (blockIdx.x == 0) {
            for (int vv = wrp; vv < 29; vv += NWARP) {
                double s = 0.0;
                for (int b2 = lane; b2 < grid; b2 += 32) s += g_part[vv][b2];
                #pragma unroll
                for (int o = 16; o; o >>= 1) s += __shfl_xor_sync(0xffffffffu, s, o);
                if (lane == 0) red[vv] = s;
            }
            __syncthreads();
            if (wrp == 0) {
                if (lane == 0) {
                    double cost = 0.5 * red[27] / fmax(red[28], 1.0);
                    if (step == 0) {
                        sprev = cost;
                        for (int i = 0; i < 27; i++) sGH[i] = red[i];
                        for (int i = 0; i < 9; i++) sRcur[i] = R0[i];
                        for (int i = 0; i < 3; i++) stcur[i] = t0[i];
                        sstate[0] = 0.01f; sstate[1] = 1.0f;
                    } else {
                        bool accept = (cost <= sprev);
                        float lam = sstate[0] * (accept ? 0.1f : 10.0f);
                        sstate[0] = fminf(fmaxf(lam, 1e-6f), 1e4f);
                        sstate[1] = accept ? 1.0f : fminf(fmaxf(0.1f * sstate[1], 1e-3f), 1.0f);
                        if (accept) {
                            for (int i = 0; i < 27; i++) sGH[i] = red[i];
                            for (int i = 0; i < 9; i++) sRcur[i] = g_Rc[i];
                            for (int i = 0; i < 3; i++) stcur[i] = g_tc[i];
                            sprev = cost;
                        }
                    }
                }
                __syncwarp();
                if (step < NITERS) {
                    warp_solve(sGH, sstate[0], sstate[1], sRcur, stcur, lane);
                } else if (lane == 0) {
                    for (int i = 0; i < 9; i++) out[i] = sRcur[i];
                    for (int i = 0; i < 3; i++) out[9 + i] = stcur[i];
                }
            }
        }
        gbar(grid);
    }
}

// ---------------- launch ----------------
extern "C" void kernel_launch(void* const* d_in, const int* in_sizes, int n_in,
                              void* d_out, int out_size)
{
    const float* pts  = (const float*)d_in[0];   // pts3D (N,3)
    const float* fref = (const float*)d_in[1];   // feature_ref (N,C)
    const float* fm   = (const float*)d_in[2];   // feature_map_query (C,H,W)
    const float* gx   = (const float*)d_in[3];   // feature_grad_x
    const float* gy   = (const float*)d_in[4];   // feature_grad_y
    const float* Km   = (const float*)d_in[5];   // K (3,3)
    const float* R0   = (const float*)d_in[6];   // R_init
    const float* t0   = (const float*)d_in[7];   // t_init

    transpose_kernel<<<(HW / 32) * 3, 256>>>(fm, gx, gy);

    // Size the persistent grid to guaranteed co-residency (deadlock-safe barrier).
    int dev = 0;
    cudaGetDevice(&dev);
    int nsm = 148;
    cudaDeviceGetAttribute(&nsm, cudaDevAttrMultiProcessorCount, dev);
    int maxb = 0;
    cudaOccupancyMaxActiveBlocksPerMultiprocessor(&maxb, mega_kernel, MTHREADS, 0);
    if (maxb < 1) maxb = 1;
    int grid = nsm * maxb;
    if (grid > MAXB) grid = MAXB;

    mega_kernel<<<grid, MTHREADS>>>(pts, fref, Km, R0, t0, (float*)d_out, grid);
}

// round 11
// speedup vs baseline: 1.2295x; 1.2295x over previous
#include <cuda_runtime.h>
#include <math.h>

// Problem constants (fixed benchmark shapes)
#define N_PTS   50000
#define C_FEAT  128
#define HF      480
#define WF      640
#define IMW     640
#define IMH     480
#define HW      (HF*WF)
#define NITERS  10

#define MTHREADS 768
#define NWARP    (MTHREADS/32)    // 24
#define MAXB     192

// ---------------- persistent device state ----------------
// Packed pixel-major maps: per pixel 96 float4 = [fm(32 f4) | gx(32 f4) | gy(32 f4)]
__device__ float4 g_packed[(size_t)HW * 96];

__device__ double   g_part[29][MAXB];   // [stat][block], coalesced cross-block reads
__device__ unsigned g_count = 0;        // barrier arrival counter (reset by releaser)
__device__ unsigned g_gen   = 0;        // barrier generation (monotonic, replay-safe)

// Hessian upper-triangle index maps (21 entries)
__device__ const int c_hk[21] = {0,0,0,0,0,0,1,1,1,1,1,2,2,2,2,3,3,3,4,4,5};
__device__ const int c_hl[21] = {0,1,2,3,4,5,1,2,3,4,5,2,3,4,5,3,4,5,4,5,5};

// ---------------- transpose (C,H,W) x3 -> (pix, map, C) ----------------
__global__ __launch_bounds__(256) void transpose_kernel(
    const float* __restrict__ fm, const float* __restrict__ gx, const float* __restrict__ gy)
{
    __shared__ float sh[32][C_FEAT + 1];
    int b    = blockIdx.x;            // (HW/32)*3 blocks
    int map  = b / (HW / 32);
    int tile = b % (HW / 32);
    int pix0 = tile * 32;
    const float* src = (map == 0) ? fm : (map == 1) ? gx : gy;

    int t = threadIdx.x, lane = t & 31, grp = t >> 5;   // 8 groups
    #pragma unroll
    for (int cb = 0; cb < C_FEAT; cb += 8) {
        int ch = cb + grp;
        sh[lane][ch] = src[(size_t)ch * HW + pix0 + lane];
    }
    __syncthreads();
    float* out = (float*)g_packed;
    #pragma unroll
    for (int pb = 0; pb < 32; pb += 8) {
        int p = pb + grp;
        size_t base = (size_t)(pix0 + p) * 384 + (size_t)map * 128;
        #pragma unroll
        for (int k = 0; k < 4; k++)
            out[base + k * 32 + lane] = sh[p][k * 32 + lane];
    }
}

// ---------------- software grid barrier ----------------
__device__ __forceinline__ void gbar(int grid) {
    __syncthreads();
    if (threadIdx.x == 0) {
        unsigned gen = *(volatile unsigned*)&g_gen;
        __threadfence();
        unsigned old = atomicAdd(&g_count, 1u);
        if (old == (unsigned)grid - 1u) {
            g_count = 0;
            __threadfence();
            atomicAdd(&g_gen, 1u);
        } else {
            while (*(volatile unsigned*)&g_gen == gen) { }
        }
        __threadfence();
    }
    __syncthreads();
}

// ---------------- warp-parallel 6x6 LM solve + pose compose ----------------
// Rows on lanes 0..5; deterministic pivoting. Writes candidate pose to smem.
__device__ __forceinline__ void warp_solve(
    const double* __restrict__ GH, float lam_f, float lr_f,
    const float* __restrict__ Rcur, const float* __restrict__ tcur,
    float* __restrict__ Rc_out, float* __restrict__ tc_out, int lane)
{
    double row[7];
    #pragma unroll
    for (int j = 0; j < 7; j++) row[j] = 0.0;
    if (lane < 6) {
        #pragma unroll
        for (int j = 0; j < 6; j++) {
            int k = lane < j ? lane : j;
            int l = lane < j ? j : lane;
            int idx = 6 + (6*k - (k*(k-1))/2) + (l - k);
            row[j] = GH[idx];
        }
        row[6] = GH[lane];
        double lam = (double)lam_f;
        row[lane] += lam * (row[lane] + 1e-9);
    }

    for (int k = 0; k < 6; k++) {
        double av = (lane < 6 && lane >= k) ? fabs(row[k]) : -1.0;
        int best = lane;
        #pragma unroll
        for (int o = 16; o; o >>= 1) {
            double av2 = __shfl_xor_sync(0xffffffffu, av, o);
            int    b2  = __shfl_xor_sync(0xffffffffu, best, o);
            if (av2 > av || (av2 == av && b2 < best)) { av = av2; best = b2; }
        }
        int p = best;
        if (p != k) {
            #pragma unroll
            for (int j = 0; j < 7; j++) {
                double vk = __shfl_sync(0xffffffffu, row[j], k);
                double vp = __shfl_sync(0xffffffffu, row[j], p);
                if (lane == k) row[j] = vp;
                else if (lane == p) row[j] = vk;
            }
        }
        double pivval = __shfl_sync(0xffffffffu, row[k], k);
        double inv = 1.0 / pivval;
        if (lane == k) {
            #pragma unroll
            for (int j = 0; j < 7; j++) row[j] *= inv;
        }
        double prow[7];
        #pragma unroll
        for (int j = 0; j < 7; j++) prow[j] = __shfl_sync(0xffffffffu, row[j], k);
        if (lane < 6 && lane != k) {
            double f = row[k];
            #pragma unroll
            for (int j = 0; j < 7; j++) row[j] -= f * prow[j];
        }
    }

    double xr = row[6];
    double x[6];
    #pragma unroll
    for (int j = 0; j < 6; j++) x[j] = __shfl_sync(0xffffffffu, xr, j);

    if (lane == 0) {
        double lr = (double)lr_f;
        double dt0 = -lr * x[0], dt1 = -lr * x[1], dt2 = -lr * x[2];
        double w0  = -lr * x[3], w1  = -lr * x[4], w2  = -lr * x[5];

        double th2 = w0*w0 + w1*w1 + w2*w2;
        double th  = sqrt(th2 + 1e-24);
        double a, b;
        if (th < 1e-4) { a = 1.0 - th2 / 6.0; b = 0.5 - th2 / 24.0; }
        else           { a = sin(th) / th;    b = (1.0 - cos(th)) / (th2 + 1e-24); }
        double W[9]  = {0, -w2, w1,  w2, 0, -w0,  -w1, w0, 0};
        double W2[9];
        for (int r = 0; r < 3; r++)
            for (int c = 0; c < 3; c++) {
                double s = 0;
                for (int kq = 0; kq < 3; kq++) s += W[r*3+kq] * W[kq*3+c];
                W2[r*3+c] = s;
            }
        double dr[9];
        for (int i = 0; i < 9; i++) dr[i] = a * W[i] + b * W2[i];
        dr[0] += 1.0; dr[4] += 1.0; dr[8] += 1.0;

        double Rc[9], tc[3];
        for (int r = 0; r < 3; r++)
            for (int c = 0; c < 3; c++) {
                double s = 0;
                for (int kq = 0; kq < 3; kq++) s += dr[r*3+kq] * (double)Rcur[kq*3+c];
                Rc[r*3+c] = s;
            }
        for (int r = 0; r < 3; r++) {
            double s = 0;
            for (int kq = 0; kq < 3; kq++) s += dr[r*3+kq] * (double)tcur[kq];
            tc[r] = s;
        }
        tc[0] += dt0; tc[1] += dt1; tc[2] += dt2;

        for (int i = 0; i < 9; i++) Rc_out[i] = (float)Rc[i];
        for (int i = 0; i < 3; i++) tc_out[i] = (float)tc[i];
    }
}

// ---------------- persistent mega-kernel (1 block per SM) ----------------
__global__ __launch_bounds__(MTHREADS, 1)
void mega_kernel(const float* __restrict__ pts, const float* __restrict__ fref,
                 const float* __restrict__ Kmat, const float* __restrict__ R0,
                 const float* __restrict__ t0, float* __restrict__ out, int grid)
{
    __shared__ int    s_pix[MTHREADS];
    __shared__ float  s_X[MTHREADS], s_Y[MTHREADS], s_Z[MTHREADS];
    __shared__ int    s_idx[MTHREADS];
    __shared__ int    s_wcnt[NWARP];
    __shared__ double sred[NWARP][29];
    __shared__ double red[29];
    __shared__ double sGH[27];
    __shared__ float  sRcur[9], stcur[3];   // accepted pose (replicated per block)
    __shared__ float  sRc[9], stc[3];       // candidate pose (replicated per block)
    __shared__ float  sstate[2];            // lam, lr
    __shared__ double sprev;

    const float fx = Kmat[0], cx = Kmat[2], fy = Kmat[4], cy = Kmat[5];
    const int lane = threadIdx.x & 31;
    const int wrp  = threadIdx.x >> 5;
    const float4* frf4 = (const float4*)fref;

    int kk = 0, ll = 0;
    if (lane >= 6 && lane < 27) { kk = c_hk[lane - 6]; ll = c_hl[lane - 6]; }

    const int chunk = (N_PTS + grid - 1) / grid;
    const int base  = blockIdx.x * chunk;
    const int myn   = (base < N_PTS) ? min(chunk, N_PTS - base) : 0;

    for (int step = 0; step <= NITERS; step++) {
        const bool doGH = (step < NITERS);
        // ---- pose to evaluate (init pose or locally-computed candidate) ----
        float Rl[9], tl[3];
        if (step == 0) {
            #pragma unroll
            for (int i = 0; i < 9; i++) Rl[i] = R0[i];
            #pragma unroll
            for (int i = 0; i < 3; i++) tl[i] = t0[i];
        } else {
            #pragma unroll
            for (int i = 0; i < 9; i++) Rl[i] = sRc[i];
            #pragma unroll
            for (int i = 0; i < 3; i++) tl[i] = stc[i];
        }
        __syncthreads();   // everyone has read the pose before smem reuse below

        double acc = 0.0, acost = 0.0;
        int    validtot = 0;

        for (int tb = 0; tb < myn; tb += MTHREADS) {
            // ===== Phase A: thread-parallel projection + deterministic compaction =====
            int tloc = tb + threadIdx.x;
            bool valid = false;
            float X = 0.f, Y = 0.f, Z = 0.f;
            int pix = 0;
            if (tloc < myn) {
                int i = base + tloc;
                float X0 = pts[3*i], Y0 = pts[3*i+1], Z0 = pts[3*i+2];
                X = Rl[0]*X0 + Rl[1]*Y0 + Rl[2]*Z0 + tl[0];
                Y = Rl[3]*X0 + Rl[4]*Y0 + Rl[5]*Z0 + tl[1];
                Z = Rl[6]*X0 + Rl[7]*Y0 + Rl[8]*Z0 + tl[2];
                float u = (fx*X + cx*Z) / Z;
                float v = (fy*Y + cy*Z) / Z;
                u = fminf(fmaxf(u, -1e6f), 1e6f);
                v = fminf(fmaxf(v, -1e6f), 1e6f);
                int px = (int)rintf(u) - 1;
                int py = (int)rintf(v) - 1;
                valid = (px >= 0) && (py >= 0) && (px < IMW) && (py < IMH);
                pix = py * WF + px;
            }
            unsigned bal = __ballot_sync(0xffffffffu, valid);
            if (lane == 0) s_wcnt[wrp] = __popc(bal);
            __syncthreads();
            int off = 0, total = 0;
            #pragma unroll
            for (int w2 = 0; w2 < NWARP; w2++) {
                int c2 = s_wcnt[w2];
                if (w2 < wrp) off += c2;
                total += c2;
            }
            int pos = off + __popc(bal & ((1u << lane) - 1u));
            if (valid) {
                s_pix[pos] = pix; s_X[pos] = X; s_Y[pos] = Y; s_Z[pos] = Z;
                s_idx[pos] = base + tloc;
            }
            __syncthreads();
            validtot += total;

            // ===== Phase B: warps walk compacted list with 1-ahead register prefetch =====
            int j = wrp;
            float4 f, a, bb, fr;
            if (j < total) {
                const float4* pb = g_packed + (size_t)s_pix[j] * 96;
                f  = pb[lane];
                fr = frf4[(size_t)s_idx[j] * 32 + lane];
                if (doGH) { a = pb[32 + lane]; bb = pb[64 + lane]; }
            }
            while (j < total) {
                int jn = j + NWARP;
                float4 fN, aN, bN, frN;
                if (jn < total) {
                    const float4* pn = g_packed + (size_t)s_pix[jn] * 96;
                    fN  = pn[lane];
                    frN = frf4[(size_t)s_idx[jn] * 32 + lane];
                    if (doGH) { aN = pn[32 + lane]; bN = pn[64 + lane]; }
                }

                float ex = f.x - fr.x, ey = f.y - fr.y, ez = f.z - fr.z, ew = f.w - fr.w;
                acost += (double)(ex*ex + ey*ey + ez*ez + ew*ew);

                if (doGH) {
                    float sxx = a.x*a.x + a.y*a.y + a.z*a.z + a.w*a.w;
                    float syy = bb.x*bb.x + bb.y*bb.y + bb.z*bb.z + bb.w*bb.w;
                    float sxy = a.x*bb.x + a.y*bb.y + a.z*bb.z + a.w*bb.w;
                    float sxe = a.x*ex + a.y*ey + a.z*ez + a.w*ew;
                    float sye = bb.x*ex + bb.y*ey + bb.z*ez + bb.w*ew;
                    #pragma unroll
                    for (int o = 16; o; o >>= 1) {
                        sxx += __shfl_xor_sync(0xffffffffu, sxx, o);
                        syy += __shfl_xor_sync(0xffffffffu, syy, o);
                        sxy += __shfl_xor_sync(0xffffffffu, sxy, o);
                        sxe += __shfl_xor_sync(0xffffffffu, sxe, o);
                        sye += __shfl_xor_sync(0xffffffffu, sye, o);
                    }

                    float Xp = s_X[j], Yp = s_Y[j], Zp = s_Z[j];
                    float Zs  = (fabsf(Zp) > 1e-6f) ? Zp : 1e-6f;
                    float iz  = 1.0f / Zs;
                    float iz2 = iz * iz;
                    float A00 =  fx * iz,                 A01 = 0.0f,                    A02 = -fx * Xp * iz2;
                    float A03 = -fx * Xp * Yp * iz2,      A04 = fx*Zp*iz + fx*Xp*Xp*iz2, A05 = -fx * Yp * iz;
                    float A10 = 0.0f,                     A11 = fy * iz,                 A12 = -fy * Yp * iz2;
                    float A13 = -fy*Zp*iz - fy*Yp*Yp*iz2, A14 = fy * Xp * Yp * iz2,      A15 =  fy * Xp * iz;

                    float a0 = (lane==0)?A00:(lane==1)?A01:(lane==2)?A02:(lane==3)?A03:(lane==4)?A04:A05;
                    float a1 = (lane==0)?A10:(lane==1)?A11:(lane==2)?A12:(lane==3)?A13:(lane==4)?A14:A15;
                    float A0k = __shfl_sync(0xffffffffu, a0, kk);
                    float A0l = __shfl_sync(0xffffffffu, a0, ll);
                    float A1k = __shfl_sync(0xffffffffu, a1, kk);
                    float A1l = __shfl_sync(0xffffffffu, a1, ll);

                    float term;
                    if (lane < 6) term = sxe * a0 + sye * a1;
                    else          term = sxx*A0k*A0l + sxy*(A0k*A1l + A1k*A0l) + syy*A1k*A1l;
                    if (lane < 27) acc += (double)term;
                }

                f = fN; a = aN; bb = bN; fr = frN;
                j = jn;
            }
            __syncthreads();   // protect smem before next tile's Phase A
        }

        // ---- block-level reduce & publish partials ----
        #pragma unroll
        for (int o = 16; o; o >>= 1)
            acost += __shfl_xor_sync(0xffffffffu, acost, o);
        if (lane < 27) sred[wrp][lane] = acc;
        if (lane == 0) sred[wrp][27] = acost;
        __syncthreads();
        if (threadIdx.x < 28) {
            double s = 0.0;
            #pragma unroll
            for (int jj = 0; jj < NWARP; jj++) s += sred[jj][threadIdx.x];
            g_part[threadIdx.x][blockIdx.x] = s;
        }
        if (threadIdx.x == 28) g_part[28][blockIdx.x] = (double)validtot;

        // ---- ONE grid barrier per step ----
        gbar(grid);

        // ---- ALL blocks: identical redundant reduce + accept + solve ----
        for (int vv = wrp; vv < 29; vv += NWARP) {
            double s = 0.0;
            for (int b2 = lane; b2 < grid; b2 += 32) s += g_part[vv][b2];
            #pragma unroll
            for (int o = 16; o; o >>= 1) s += __shfl_xor_sync(0xffffffffu, s, o);
            if (lane == 0) red[vv] = s;
        }
        __syncthreads();
        if (wrp == 0) {
            if (lane == 0) {
                double cost = 0.5 * red[27] / fmax(red[28], 1.0);
                if (step == 0) {
                    sprev = cost;
                    for (int i = 0; i < 27; i++) sGH[i] = red[i];
                    for (int i = 0; i < 9; i++) sRcur[i] = R0[i];
                    for (int i = 0; i < 3; i++) stcur[i] = t0[i];
                    sstate[0] = 0.01f; sstate[1] = 1.0f;
                } else {
                    bool accept = (cost <= sprev);
                    float lam = sstate[0] * (accept ? 0.1f : 10.0f);
                    sstate[0] = fminf(fmaxf(lam, 1e-6f), 1e4f);
                    sstate[1] = accept ? 1.0f : fminf(fmaxf(0.1f * sstate[1], 1e-3f), 1.0f);
                    if (accept) {
                        for (int i = 0; i < 27; i++) sGH[i] = red[i];
                        for (int i = 0; i < 9; i++) sRcur[i] = sRc[i];
                        for (int i = 0; i < 3; i++) stcur[i] = stc[i];
                        sprev = cost;
                    }
                }
            }
            __syncwarp();
            if (step < NITERS) {
                warp_solve(sGH, sstate[0], sstate[1], sRcur, stcur, sRc, stc, lane);
            } else if (blockIdx.x == 0 && lane == 0) {
                for (int i = 0; i < 9; i++) out[i] = sRcur[i];
                for (int i = 0; i < 3; i++) out[9 + i] = stcur[i];
            }
        }
        __syncthreads();   // candidate pose visible to whole block before next step
    }
}

// ---------------- launch ----------------
extern "C" void kernel_launch(void* const* d_in, const int* in_sizes, int n_in,
                              void* d_out, int out_size)
{
    const float* pts  = (const float*)d_in[0];   // pts3D (N,3)
    const float* fref = (const float*)d_in[1];   // feature_ref (N,C)
    const float* fm   = (const float*)d_in[2];   // feature_map_query (C,H,W)
    const float* gx   = (const float*)d_in[3];   // feature_grad_x
    const float* gy   = (const float*)d_in[4];   // feature_grad_y
    const float* Km   = (const float*)d_in[5];   // K (3,3)
    const float* R0   = (const float*)d_in[6];   // R_init
    const float* t0   = (const float*)d_in[7];   // t_init

    transpose_kernel<<<(HW / 32) * 3, 256>>>(fm, gx, gy);

    // One block per SM, guaranteed co-resident (deadlock-safe barrier).
    int dev = 0;
    cudaGetDevice(&dev);
    int nsm = 148;
    cudaDeviceGetAttribute(&nsm, cudaDevAttrMultiProcessorCount, dev);
    int maxb = 0;
    cudaOccupancyMaxActiveBlocksPerMultiprocessor(&maxb, mega_kernel, MTHREADS, 0);
    if (maxb < 1) maxb = 1;   // (regs fit: <=85 regs @768 threads)
    int grid = nsm;
    if (grid > MAXB) grid = MAXB;

    mega_kernel<<<grid, MTHREADS>>>(pts, fref, Km, R0, t0, (float*)d_out, grid);
}